// round 13
// baseline (speedup 1.0000x reference)
#include <cuda_runtime.h>
#include <math.h>

#define BATCH 32
#define SEQT  512
#define HID   512
#define G4    2048   // 4*HID

// out layout (fp32): out[B][T][2H] @0, h_n[2][B][H] @16777216, c_n @16809984
#define OUT_HN 16777216
#define OUT_CN 16809984

// ---------------------------------------------------------------------------
// Device globals (allocation-free scratch), 256B-aligned for vector access.
// ---------------------------------------------------------------------------
// gx permuted per consumer block: [dir][blk(128)][t(512)][cl(16)][b(32)]
__device__ __align__(256) float g_gx[2][128][SEQT][16][32];
__device__ __align__(256) float g_hB[2][2][BATCH][HID];   // [parity][dir][batch][unit]
// grouped step counters: 8 counters/dir (16 blocks each), one 128B line apiece
__device__ __align__(256) int   g_cnt[2][8][32];

// ---------------------------------------------------------------------------
// Packed fp32x2 FMA (Blackwell FFMA2; only reachable via PTX)
// ---------------------------------------------------------------------------
__device__ __forceinline__ float2 f2fma(float2 a, float2 b, float2 c) {
    unsigned long long ra = *reinterpret_cast<unsigned long long*>(&a);
    unsigned long long rb = *reinterpret_cast<unsigned long long*>(&b);
    unsigned long long rc = *reinterpret_cast<unsigned long long*>(&c);
    unsigned long long rd;
    asm("fma.rn.f32x2 %0, %1, %2, %3;" : "=l"(rd) : "l"(ra), "l"(rb), "l"(rc));
    return *reinterpret_cast<float2*>(&rd);
}
__device__ __forceinline__ float2 f2(float x, float y) { return make_float2(x, y); }

__device__ __forceinline__ float sigf(float x) { return 1.0f / (1.0f + __expf(-x)); }
__device__ __forceinline__ float tanhx(float x) { return 2.0f / (1.0f + __expf(-2.0f * x)) - 1.0f; }

// ---------------------------------------------------------------------------
// Phase 1: gx = x @ W_ih^T + biases (written permuted for 128-block consumers).
// Init of h/counters is embedded. BM=BN=64, BK=16, 256 thr, dup'd-A f32x2.
// ---------------------------------------------------------------------------
#define BM 64
#define BN 64
#define BK 16

__global__ __launch_bounds__(256) void gemm_ih_kernel(
        const float* __restrict__ x,
        const float* __restrict__ h0,
        const float* __restrict__ w_f, const float* __restrict__ w_r,
        const float* __restrict__ bi_f, const float* __restrict__ bh_f,
        const float* __restrict__ bi_r, const float* __restrict__ bh_r) {
    const int tid = threadIdx.x;

    // ---- embedded init (h0 -> g_hB[0] (identical linear layout), counters) ----
    {
        const int gid = (blockIdx.z * gridDim.y + blockIdx.y) * gridDim.x + blockIdx.x;
        if (gid < 128) {
            const int idx = gid * 256 + tid;     // 0..32767
            (&g_hB[0][0][0][0])[idx] = h0[idx];  // [dir][b][j] matches h0 layout
        }
        if (gid == 0 && tid < 16) g_cnt[tid >> 3][tid & 7][0] = 0;
    }

    const int dir = blockIdx.z;
    const float* __restrict__ w  = dir ? w_r  : w_f;
    const float* __restrict__ bi = dir ? bi_r : bi_f;
    const float* __restrict__ bh = dir ? bh_r : bh_f;

    const int rm0 = blockIdx.y * BM;   // rows over T*B (row = t*32+b)
    const int cn0 = blockIdx.x * BN;   // cols over 4H

    __shared__ __align__(16) float2 Asd[BK][BM + 2];   // A rows, duplicated lanes
    __shared__ __align__(16) float  Ws[BK][BN + 4];

    const int tr = tid / 16;           // 0..15 row group
    const int tc = tid % 16;           // 0..15 col group

    const int l_row = tid >> 2;        // 0..63
    const int l_k4  = (tid & 3) << 2;  // 0,4,8,12

    const int r  = rm0 + l_row;
    int       tt = r >> 5;
    const int bb = r & 31;
    if (dir) tt = (SEQT - 1) - tt;
    const float* a_ptr = x + ((size_t)bb * SEQT + tt) * HID;
    const float* w_ptr = w + (size_t)(cn0 + l_row) * HID;

    float2 acc[4][2];
#pragma unroll
    for (int i = 0; i < 4; i++) { acc[i][0] = f2(0.f, 0.f); acc[i][1] = f2(0.f, 0.f); }

    for (int k0 = 0; k0 < HID; k0 += BK) {
        float4 av = *(const float4*)(a_ptr + k0 + l_k4);
        float4 wv = *(const float4*)(w_ptr + k0 + l_k4);
        __syncthreads();
        Asd[l_k4 + 0][l_row] = f2(av.x, av.x);
        Asd[l_k4 + 1][l_row] = f2(av.y, av.y);
        Asd[l_k4 + 2][l_row] = f2(av.z, av.z);
        Asd[l_k4 + 3][l_row] = f2(av.w, av.w);
        Ws[l_k4 + 0][l_row] = wv.x;
        Ws[l_k4 + 1][l_row] = wv.y;
        Ws[l_k4 + 2][l_row] = wv.z;
        Ws[l_k4 + 3][l_row] = wv.w;
        __syncthreads();
#pragma unroll
        for (int kk = 0; kk < BK; kk++) {
            float4 ad0 = *(const float4*)&Asd[kk][tr * 4];
            float4 ad1 = *(const float4*)&Asd[kk][tr * 4 + 2];
            float4 w4  = *(const float4*)&Ws[kk][tc * 4];
            float2 w01 = f2(w4.x, w4.y);
            float2 w23 = f2(w4.z, w4.w);
            float2 a0 = f2(ad0.x, ad0.y);
            float2 a1 = f2(ad0.z, ad0.w);
            float2 a2 = f2(ad1.x, ad1.y);
            float2 a3 = f2(ad1.z, ad1.w);
            acc[0][0] = f2fma(a0, w01, acc[0][0]); acc[0][1] = f2fma(a0, w23, acc[0][1]);
            acc[1][0] = f2fma(a1, w01, acc[1][0]); acc[1][1] = f2fma(a1, w23, acc[1][1]);
            acc[2][0] = f2fma(a2, w01, acc[2][0]); acc[2][1] = f2fma(a2, w23, acc[2][1]);
            acc[3][0] = f2fma(a3, w01, acc[3][0]); acc[3][1] = f2fma(a3, w23, acc[3][1]);
        }
    }

    // epilogue: permuted gx. col c -> unit=c&511, gate=c>>9;
    //           blk = unit>>2, cl = gate*4 + (unit&3)
    const int cc = cn0 + tc * 4;
    float bsum[4], res[4];
#pragma unroll
    for (int j = 0; j < 4; j++) bsum[j] = bi[cc + j] + bh[cc + j];
#pragma unroll
    for (int i = 0; i < 4; i++) {
        const int rr = rm0 + tr * 4 + i;
        const int t = rr >> 5;
        const int b = rr & 31;
        res[0] = acc[i][0].x + bsum[0];
        res[1] = acc[i][0].y + bsum[1];
        res[2] = acc[i][1].x + bsum[2];
        res[3] = acc[i][1].y + bsum[3];
#pragma unroll
        for (int j = 0; j < 4; j++) {
            const int c = cc + j;
            const int unit = c & 511;
            const int gate = c >> 9;
            const int blk = unit >> 2;
            const int cl = gate * 4 + (unit & 3);
            g_gx[dir][blk][t][cl][b] = res[j];
        }
    }
}

// ---------------------------------------------------------------------------
// Phase 2: persistent recurrence. 128 blocks, 256 threads; each block owns
// 4 hidden units of BOTH directions and alternates dir phases per step —
// the dir-1 phase hides the dir-0 inter-block wait and vice versa.
// W in registers (both dirs); 4-col butterfly reduce; grouped counters.
// ---------------------------------------------------------------------------
#define NBLK 128
#define PST 33                     // P row stride (floats); scalar access only

#define SM_HS 0                    // float Hs[32][512] = 65536 B
#define SM_P  65536                // float P[16][33]   =  2112 B
#define SM_HO 67648                // float HO[32][4]   =   512 B
#define SMEM_TOTAL (67648 + 512)

__global__ __launch_bounds__(256, 1)
void lstm_persistent_kernel(const float* __restrict__ w_hh_f,
                            const float* __restrict__ w_hh_r,
                            const float* __restrict__ c0,
                            float* __restrict__ out) {
    extern __shared__ __align__(16) char smem_raw[];
    float* Hs = (float*)(smem_raw + SM_HS);    // [b][k], stride 512
    float* P  = (float*)(smem_raw + SM_P);     // [cl][b], stride PST
    float* HO = (float*)(smem_raw + SM_HO);    // [b][4]

    const int tid = threadIdx.x;
    const int blk = blockIdx.x;                // 0..127
    const int j0  = blk * 4;

    const int wid  = tid >> 5;                 // 0..7
    const int lane = tid & 31;
    const int hb = wid >> 2;                   // batch half
    const int cq = wid & 3;                    // gate

    // ---- W registers for BOTH dirs: wreg[d][c8][jp] ----
    float2 wreg[2][4][8];
#pragma unroll
    for (int d = 0; d < 2; d++) {
        const float* wd = d ? w_hh_r : w_hh_f;
#pragma unroll
        for (int c8 = 0; c8 < 4; c8++) {
            const float* wr = wd + (size_t)(cq * HID + j0 + c8) * HID;
#pragma unroll
            for (int jp = 0; jp < 8; jp++)
                wreg[d][c8][jp] = f2(wr[jp * 64 + lane], wr[jp * 64 + 32 + lane]);
        }
    }

    // butterfly constants: 4 cols; cmap over lane bits {4,3}; owner lane&7==0
    const bool hi16 = (lane & 16) != 0;
    const bool hi8  = (lane & 8)  != 0;
    const bool owner = (lane & 7) == 0;
    const int  cmap = ((lane >> 4) & 1) * 2 + ((lane >> 3) & 1);
    float* pdst = &P[(cq * 4 + cmap) * PST + hb * 16];

    // pointwise ownership (threads 0..127): u = wid (0..3), b = lane
    const bool pw = tid < 128;
    const int pu = wid & 3;
    const int pb = lane;
    float creg[2];
#pragma unroll
    for (int d = 0; d < 2; d++)
        creg[d] = pw ? c0[((size_t)d * BATCH + pb) * HID + j0 + pu] : 0.f;

    float4* Hs4 = (float4*)Hs;
    const int grp = blk >> 4;                  // 8 groups of 16 blocks

    __syncthreads();

    for (int t = 0; t < SEQT; t++) {
#pragma unroll
        for (int d = 0; d < 2; d++) {
            // prefetch gx for this dir (coalesced; in flight during the wait)
            const float* gxp = &g_gx[d][blk][t][0][0];
            float gxr0 = 0.f, gxr1 = 0.f, gxr2 = 0.f, gxr3 = 0.f;
            if (pw) {
                gxr0 = gxp[(pu)      * 32 + pb];
                gxr1 = gxp[(4 + pu)  * 32 + pb];
                gxr2 = gxp[(8 + pu)  * 32 + pb];
                gxr3 = gxp[(12 + pu) * 32 + pb];
            }

            // wait: 8 lanes poll 8 grouped counters (16 blocks each)
            if (t > 0 && tid < 8) {
                int* pc = &g_cnt[d][tid][0];
                const int target = 16 * t;
                int v;
                do {
                    asm volatile("ld.acquire.gpu.s32 %0, [%1];" : "=r"(v) : "l"(pc));
                } while (v < target);
            }
            __syncthreads();

            // stage h (64KB) into Hs[b][k] — linear coalesced copy
            const float4* src = (const float4*)&g_hB[t & 1][d][0][0];
#pragma unroll
            for (int it = 0; it < 16; it++) Hs4[it * 256 + tid] = src[it * 256 + tid];
            __syncthreads();

            // GEMM: 16 batches x 4 cols x 512 k (lane = k%32, jp = k/64)
            const float* hbase = Hs + (hb * 16) * 512 + lane;
#pragma unroll 4
            for (int bi = 0; bi < 16; bi++) {
                const float* hp = hbase + bi * 512;
                float2 a0 = f2(0.f, 0.f), a1 = f2(0.f, 0.f);
                float2 a2 = f2(0.f, 0.f), a3 = f2(0.f, 0.f);
#pragma unroll
                for (int jp = 0; jp < 8; jp++) {
                    float2 hv = f2(hp[jp * 64], hp[jp * 64 + 32]);
                    a0 = f2fma(hv, wreg[d][0][jp], a0);
                    a1 = f2fma(hv, wreg[d][1][jp], a1);
                    a2 = f2fma(hv, wreg[d][2][jp], a2);
                    a3 = f2fma(hv, wreg[d][3][jp], a3);
                }
                float v0 = a0.x + a0.y, v1 = a1.x + a1.y;
                float v2 = a2.x + a2.y, v3 = a3.x + a3.y;
                // value-halving butterfly (keep col, send other)
                float k0 = hi16 ? v2 : v0, s0 = hi16 ? v0 : v2;
                float k1 = hi16 ? v3 : v1, s1 = hi16 ? v1 : v3;
                k0 += __shfl_xor_sync(0xffffffffu, s0, 16);
                k1 += __shfl_xor_sync(0xffffffffu, s1, 16);
                float m = hi8 ? k1 : k0, sm = hi8 ? k0 : k1;
                m += __shfl_xor_sync(0xffffffffu, sm, 8);
                m += __shfl_xor_sync(0xffffffffu, m, 4);
                m += __shfl_xor_sync(0xffffffffu, m, 2);
                m += __shfl_xor_sync(0xffffffffu, m, 1);
                if (owner) pdst[bi] = m;
            }
            __syncthreads();

            // pointwise: threads 0..127, one (u,b) each
            if (pw) {
                const float pi = P[(pu)      * PST + pb] + gxr0;
                const float pf = P[(4 + pu)  * PST + pb] + gxr1;
                const float pg = P[(8 + pu)  * PST + pb] + gxr2;
                const float po = P[(12 + pu) * PST + pb] + gxr3;
                const float iv = sigf(pi);
                const float fv = sigf(pf);
                const float gv = tanhx(pg);
                const float ov = sigf(po);
                creg[d] = fv * creg[d] + iv * gv;
                const float hnew = ov * tanhx(creg[d]);
                HO[pb * 4 + pu] = hnew;
                if (t == SEQT - 1) {
                    out[OUT_HN + ((size_t)d * BATCH + pb) * HID + j0 + pu] = hnew;
                    out[OUT_CN + ((size_t)d * BATCH + pb) * HID + j0 + pu] = creg[d];
                }
            }
            __syncthreads();   // HO visible

            // h write (32 threads x float4), then signal
            if (tid < 32) {
                float4 v = *(const float4*)&HO[tid * 4];
                float* hdst = &g_hB[(t & 1) ^ 1][d][0][0];
                *(float4*)&hdst[tid * HID + j0] = v;
            }
            __syncthreads();   // h stores block-wide before release

            if (tid == 0) {
                asm volatile("red.release.gpu.add.s32 [%0], %1;"
                             :: "l"(&g_cnt[d][grp][0]), "r"(1));
            }

            // out write — off the critical path
            if (tid < 32) {
                float4 v = *(const float4*)&HO[tid * 4];
                const int tout = d ? (SEQT - 1 - t) : t;
                *(float4*)&out[((size_t)tid * SEQT + tout) * (2 * HID) + d * HID + j0] = v;
            }
        }
    }
}

// ---------------------------------------------------------------------------
// Launch
// ---------------------------------------------------------------------------
extern "C" void kernel_launch(void* const* d_in, const int* in_sizes, int n_in,
                              void* d_out, int out_size) {
    const float* x      = (const float*)d_in[0];
    const float* h0     = (const float*)d_in[1];
    const float* c0     = (const float*)d_in[2];
    const float* w_ih_f = (const float*)d_in[3];
    const float* w_hh_f = (const float*)d_in[4];
    const float* b_ih_f = (const float*)d_in[5];
    const float* b_hh_f = (const float*)d_in[6];
    const float* w_ih_r = (const float*)d_in[7];
    const float* w_hh_r = (const float*)d_in[8];
    const float* b_ih_r = (const float*)d_in[9];
    const float* b_hh_r = (const float*)d_in[10];
    float* out = (float*)d_out;

    cudaFuncSetAttribute(lstm_persistent_kernel,
                         cudaFuncAttributeMaxDynamicSharedMemorySize, SMEM_TOTAL);

    dim3 ggrid(G4 / BN, (SEQT * BATCH) / BM, 2);   // (32, 256, 2)
    gemm_ih_kernel<<<ggrid, 256>>>(x, h0, w_ih_f, w_ih_r,
                                   b_ih_f, b_hh_f, b_ih_r, b_hh_r);

    lstm_persistent_kernel<<<NBLK, 256, SMEM_TOTAL>>>(
        w_hh_f, w_hh_r, c0, out);
}

// round 14
// speedup vs baseline: 1.3749x; 1.3749x over previous
#include <cuda_runtime.h>
#include <math.h>

#define BATCH 32
#define SEQT  512
#define HID   512
#define G4    2048   // 4*HID

// out layout (fp32): out[B][T][2H] @0, h_n[2][B][H] @16777216, c_n @16809984
#define OUT_HN 16777216
#define OUT_CN 16809984

// ---------------------------------------------------------------------------
// Device globals (allocation-free scratch), 256B-aligned for vector access.
// ---------------------------------------------------------------------------
// gx permuted per consumer block: [dir][bh][blk(32)][t][cl(64)][bl(16)]
__device__ __align__(256) float g_gx[2][2][32][SEQT][64][16];
// h ping-pong: [parity][dir][bh][bl(16)][unit(512)] (linear == h0 layout)
__device__ __align__(256) float g_hB[2][2][2][16][HID];
// grouped step counters: stream=(dir,bh): 4 groups x 8 blocks, 128B line each
__device__ __align__(256) int   g_cnt[2][2][4][32];

// ---------------------------------------------------------------------------
// Packed fp32x2 FMA (Blackwell FFMA2; only reachable via PTX)
// ---------------------------------------------------------------------------
__device__ __forceinline__ float2 f2fma(float2 a, float2 b, float2 c) {
    unsigned long long ra = *reinterpret_cast<unsigned long long*>(&a);
    unsigned long long rb = *reinterpret_cast<unsigned long long*>(&b);
    unsigned long long rc = *reinterpret_cast<unsigned long long*>(&c);
    unsigned long long rd;
    asm("fma.rn.f32x2 %0, %1, %2, %3;" : "=l"(rd) : "l"(ra), "l"(rb), "l"(rc));
    return *reinterpret_cast<float2*>(&rd);
}
__device__ __forceinline__ float2 f2(float x, float y) { return make_float2(x, y); }

__device__ __forceinline__ float sigf(float x) { return 1.0f / (1.0f + __expf(-x)); }
__device__ __forceinline__ float tanhx(float x) { return 2.0f / (1.0f + __expf(-2.0f * x)) - 1.0f; }

// ---------------------------------------------------------------------------
// Phase 1: gx = x @ W_ih^T + biases (written permuted). Init embedded.
// BM=BN=64, BK=16, 256 thr, 4x4 microtile, dup'd-A f32x2 (unchanged).
// ---------------------------------------------------------------------------
#define BM 64
#define BN 64
#define BK 16

__global__ __launch_bounds__(256) void gemm_ih_kernel(
        const float* __restrict__ x,
        const float* __restrict__ h0,
        const float* __restrict__ w_f, const float* __restrict__ w_r,
        const float* __restrict__ bi_f, const float* __restrict__ bh_f,
        const float* __restrict__ bi_r, const float* __restrict__ bh_r) {
    const int tid = threadIdx.x;

    // ---- embedded init (h0 -> g_hB[0] (identical linear layout), counters) ----
    {
        const int gid = (blockIdx.z * gridDim.y + blockIdx.y) * gridDim.x + blockIdx.x;
        if (gid < 128) {
            const int idx = gid * 256 + tid;     // 0..32767
            (&g_hB[0][0][0][0][0])[idx] = h0[idx];
        }
        if (gid == 0 && tid < 16)
            g_cnt[tid >> 3][(tid >> 2) & 1][tid & 3][0] = 0;
    }

    const int dir = blockIdx.z;
    const float* __restrict__ w  = dir ? w_r  : w_f;
    const float* __restrict__ bi = dir ? bi_r : bi_f;
    const float* __restrict__ bh = dir ? bh_r : bh_f;

    const int rm0 = blockIdx.y * BM;   // rows over T*B (row = t*32+b)
    const int cn0 = blockIdx.x * BN;   // cols over 4H

    __shared__ __align__(16) float2 Asd[BK][BM + 2];   // A rows, duplicated lanes
    __shared__ __align__(16) float  Ws[BK][BN + 4];

    const int tr = tid / 16;           // 0..15 row group
    const int tc = tid % 16;           // 0..15 col group

    const int l_row = tid >> 2;        // 0..63
    const int l_k4  = (tid & 3) << 2;  // 0,4,8,12

    const int r  = rm0 + l_row;
    int       tt = r >> 5;
    const int bb = r & 31;
    if (dir) tt = (SEQT - 1) - tt;
    const float* a_ptr = x + ((size_t)bb * SEQT + tt) * HID;
    const float* w_ptr = w + (size_t)(cn0 + l_row) * HID;

    float2 acc[4][2];
#pragma unroll
    for (int i = 0; i < 4; i++) { acc[i][0] = f2(0.f, 0.f); acc[i][1] = f2(0.f, 0.f); }

    for (int k0 = 0; k0 < HID; k0 += BK) {
        float4 av = *(const float4*)(a_ptr + k0 + l_k4);
        float4 wv = *(const float4*)(w_ptr + k0 + l_k4);
        __syncthreads();
        Asd[l_k4 + 0][l_row] = f2(av.x, av.x);
        Asd[l_k4 + 1][l_row] = f2(av.y, av.y);
        Asd[l_k4 + 2][l_row] = f2(av.z, av.z);
        Asd[l_k4 + 3][l_row] = f2(av.w, av.w);
        Ws[l_k4 + 0][l_row] = wv.x;
        Ws[l_k4 + 1][l_row] = wv.y;
        Ws[l_k4 + 2][l_row] = wv.z;
        Ws[l_k4 + 3][l_row] = wv.w;
        __syncthreads();
#pragma unroll
        for (int kk = 0; kk < BK; kk++) {
            float4 ad0 = *(const float4*)&Asd[kk][tr * 4];
            float4 ad1 = *(const float4*)&Asd[kk][tr * 4 + 2];
            float4 w4  = *(const float4*)&Ws[kk][tc * 4];
            float2 w01 = f2(w4.x, w4.y);
            float2 w23 = f2(w4.z, w4.w);
            float2 a0 = f2(ad0.x, ad0.y);
            float2 a1 = f2(ad0.z, ad0.w);
            float2 a2 = f2(ad1.x, ad1.y);
            float2 a3 = f2(ad1.z, ad1.w);
            acc[0][0] = f2fma(a0, w01, acc[0][0]); acc[0][1] = f2fma(a0, w23, acc[0][1]);
            acc[1][0] = f2fma(a1, w01, acc[1][0]); acc[1][1] = f2fma(a1, w23, acc[1][1]);
            acc[2][0] = f2fma(a2, w01, acc[2][0]); acc[2][1] = f2fma(a2, w23, acc[2][1]);
            acc[3][0] = f2fma(a3, w01, acc[3][0]); acc[3][1] = f2fma(a3, w23, acc[3][1]);
        }
    }

    // epilogue: permuted gx. col c: unit=c&511, gate=c>>9;
    //   blk = unit>>4, cl = gate*16 + (unit&15); bh=b>>4, bl=b&15
    const int cc = cn0 + tc * 4;
    float bsum[4], res[4];
#pragma unroll
    for (int j = 0; j < 4; j++) bsum[j] = bi[cc + j] + bh[cc + j];
#pragma unroll
    for (int i = 0; i < 4; i++) {
        const int rr = rm0 + tr * 4 + i;
        const int t = rr >> 5;
        const int b = rr & 31;
        const int bhh = b >> 4;
        const int bl = b & 15;
        res[0] = acc[i][0].x + bsum[0];
        res[1] = acc[i][0].y + bsum[1];
        res[2] = acc[i][1].x + bsum[2];
        res[3] = acc[i][1].y + bsum[3];
#pragma unroll
        for (int j = 0; j < 4; j++) {
            const int c = cc + j;
            const int unit = c & 511;
            const int gate = c >> 9;
            const int blk = unit >> 4;
            const int cl = gate * 16 + (unit & 15);
            g_gx[dir][bhh][blk][t][cl][bl] = res[j];
        }
    }
}

// ---------------------------------------------------------------------------
// Phase 2: persistent recurrence. 4 streams (dir x batch-half) x 32 blocks;
// block owns 16 units x 16 batches. W-in-registers GEMM (R10 shape),
// 32KB staging, grouped counters (4 groups x 8 blocks per stream).
// ---------------------------------------------------------------------------
#define NBLK 128
#define PST 17                     // P row stride (floats); scalar access only

#define SM_HS 0                    // float Hs[16][512] = 32768 B
#define SM_P  32768                // float P[64][17]   =  4352 B
#define SM_HO 37120                // float HO[16][16]  =  1024 B
#define SMEM_TOTAL (37120 + 1024)

__global__ __launch_bounds__(256, 1)
void lstm_persistent_kernel(const float* __restrict__ w_hh_f,
                            const float* __restrict__ w_hh_r,
                            const float* __restrict__ c0,
                            float* __restrict__ out) {
    extern __shared__ __align__(16) char smem_raw[];
    float* Hs = (float*)(smem_raw + SM_HS);    // [bl][k], stride 512
    float* P  = (float*)(smem_raw + SM_P);     // [cl][bl], stride PST
    float* HO = (float*)(smem_raw + SM_HO);    // [bl][16]

    const int tid = threadIdx.x;
    const int b128 = blockIdx.x;               // 0..127
    const int dir = b128 >> 6;
    const int bh  = (b128 >> 5) & 1;
    const int blk = b128 & 31;
    const int j0  = blk * 16;
    const float* __restrict__ w = dir ? w_hh_r : w_hh_f;

    const int wid  = tid >> 5;                 // 0..7
    const int lane = tid & 31;
    const int uh   = wid >> 2;                 // unit half (8 units)
    const int gate = wid & 3;

    // ---- W registers: warp covers cols gate*512 + [j0+uh*8, +8), lane=k%32 ----
    float2 wreg[8][8];
#pragma unroll
    for (int c8 = 0; c8 < 8; c8++) {
        const float* wr = w + (size_t)(gate * HID + j0 + uh * 8 + c8) * HID;
#pragma unroll
        for (int jp = 0; jp < 8; jp++)
            wreg[c8][jp] = f2(wr[jp * 64 + lane], wr[jp * 64 + 32 + lane]);
    }

    // butterfly constants (R10): cmap from lane bits {4,3,2}; owner lane&3==0
    const bool hi16 = (lane & 16) != 0;
    const bool hi8  = (lane & 8)  != 0;
    const bool hi4  = (lane & 4)  != 0;
    const int  cmap = ((lane >> 4) & 1) * 4 + ((lane >> 3) & 1) * 2 + ((lane >> 2) & 1);
    float* pdst = &P[(gate * 16 + uh * 8 + cmap) * PST];

    // ---- pointwise: 256 threads = 16 units x 16 batches ----
    const int pu = tid >> 4;                   // 0..15 local unit
    const int pb = tid & 15;                   // 0..15 local batch
    float creg = c0[((size_t)dir * BATCH + bh * 16 + pb) * HID + j0 + pu];

    float4* Hs4 = (float4*)Hs;
    const float* gxbase = &g_gx[dir][bh][blk][0][0][0];
    int* mycnt = &g_cnt[dir][bh][blk >> 3][0];

    __syncthreads();

    for (int t = 0; t < SEQT; t++) {
        // prefetch gx (coalesced per half-warp; in flight during the wait)
        const float* gxp = gxbase + (size_t)t * 1024;
        float gxr0 = gxp[(pu)      * 16 + pb];
        float gxr1 = gxp[(16 + pu) * 16 + pb];
        float gxr2 = gxp[(32 + pu) * 16 + pb];
        float gxr3 = gxp[(48 + pu) * 16 + pb];

        // wait: 4 lanes poll this stream's 4 grouped counters (8 blocks each)
        if (t > 0 && tid < 4) {
            int* pc = &g_cnt[dir][bh][tid][0];
            const int target = 8 * t;
            int v;
            do {
                asm volatile("ld.acquire.gpu.s32 %0, [%1];" : "=r"(v) : "l"(pc));
            } while (v < target);
        }
        __syncthreads();

        // stage h (32KB) into Hs[bl][k] — linear coalesced copy
        const float4* src = (const float4*)&g_hB[t & 1][dir][bh][0][0];
#pragma unroll
        for (int it = 0; it < 8; it++) Hs4[it * 256 + tid] = src[it * 256 + tid];
        __syncthreads();

        // GEMM: 16 batches x 8 cols x 512 k per warp (identical shape to R10)
        const float* hbase = Hs + lane;
#pragma unroll 4
        for (int bi = 0; bi < 16; bi++) {
            const float* hp = hbase + bi * 512;
            float2 a0 = f2(0.f, 0.f), a1 = f2(0.f, 0.f), a2 = f2(0.f, 0.f), a3 = f2(0.f, 0.f);
            float2 a4 = f2(0.f, 0.f), a5 = f2(0.f, 0.f), a6 = f2(0.f, 0.f), a7 = f2(0.f, 0.f);
#pragma unroll
            for (int jp = 0; jp < 8; jp++) {
                float2 hv = f2(hp[jp * 64], hp[jp * 64 + 32]);
                a0 = f2fma(hv, wreg[0][jp], a0);
                a1 = f2fma(hv, wreg[1][jp], a1);
                a2 = f2fma(hv, wreg[2][jp], a2);
                a3 = f2fma(hv, wreg[3][jp], a3);
                a4 = f2fma(hv, wreg[4][jp], a4);
                a5 = f2fma(hv, wreg[5][jp], a5);
                a6 = f2fma(hv, wreg[6][jp], a6);
                a7 = f2fma(hv, wreg[7][jp], a7);
            }
            float v0 = a0.x + a0.y, v1 = a1.x + a1.y, v2 = a2.x + a2.y, v3 = a3.x + a3.y;
            float v4 = a4.x + a4.y, v5 = a5.x + a5.y, v6 = a6.x + a6.y, v7 = a7.x + a7.y;

            // value-halving butterfly over lanes (k-residues)
            float k0 = hi16 ? v4 : v0,  s0 = hi16 ? v0 : v4;
            float k1 = hi16 ? v5 : v1,  s1 = hi16 ? v1 : v5;
            float k2 = hi16 ? v6 : v2,  s2 = hi16 ? v2 : v6;
            float k3 = hi16 ? v7 : v3,  s3 = hi16 ? v3 : v7;
            k0 += __shfl_xor_sync(0xffffffffu, s0, 16);
            k1 += __shfl_xor_sync(0xffffffffu, s1, 16);
            k2 += __shfl_xor_sync(0xffffffffu, s2, 16);
            k3 += __shfl_xor_sync(0xffffffffu, s3, 16);
            float m0 = hi8 ? k2 : k0,  t0 = hi8 ? k0 : k2;
            float m1 = hi8 ? k3 : k1,  t1 = hi8 ? k1 : k3;
            m0 += __shfl_xor_sync(0xffffffffu, t0, 8);
            m1 += __shfl_xor_sync(0xffffffffu, t1, 8);
            float m = hi4 ? m1 : m0,  u = hi4 ? m0 : m1;
            m += __shfl_xor_sync(0xffffffffu, u, 4);
            m += __shfl_xor_sync(0xffffffffu, m, 2);
            m += __shfl_xor_sync(0xffffffffu, m, 1);
            if ((lane & 3) == 0) pdst[bi] = m;
        }
        __syncthreads();

        // pointwise: 1 (unit,batch) per thread
        {
            const float pi = P[(pu)      * PST + pb] + gxr0;
            const float pf = P[(16 + pu) * PST + pb] + gxr1;
            const float pg = P[(32 + pu) * PST + pb] + gxr2;
            const float po = P[(48 + pu) * PST + pb] + gxr3;
            const float iv = sigf(pi);
            const float fv = sigf(pf);
            const float gv = tanhx(pg);
            const float ov = sigf(po);
            creg = fv * creg + iv * gv;
            const float hnew = ov * tanhx(creg);
            HO[pb * 16 + pu] = hnew;
            if (t == SEQT - 1) {
                out[OUT_HN + ((size_t)dir * BATCH + bh * 16 + pb) * HID + j0 + pu] = hnew;
                out[OUT_CN + ((size_t)dir * BATCH + bh * 16 + pb) * HID + j0 + pu] = creg;
            }
        }
        __syncthreads();   // HO visible

        // h write (64 threads x float4), then signal, then out (off crit path)
        if (tid < 64) {
            const int b  = tid >> 2;
            const int sg = (tid & 3) * 4;
            float4 v = *(const float4*)&HO[b * 16 + sg];
            float* hdst = &g_hB[(t & 1) ^ 1][dir][bh][b][0];
            *(float4*)&hdst[j0 + sg] = v;
        }
        __syncthreads();   // h stores block-wide before release

        if (tid == 0) {
            asm volatile("red.release.gpu.add.s32 [%0], %1;"
                         :: "l"(mycnt), "r"(1));
        }

        if (tid < 64) {
            const int b  = tid >> 2;
            const int sg = (tid & 3) * 4;
            float4 v = *(const float4*)&HO[b * 16 + sg];
            const int tout = dir ? (SEQT - 1 - t) : t;
            *(float4*)&out[((size_t)(bh * 16 + b) * SEQT + tout) * (2 * HID)
                           + dir * HID + j0 + sg] = v;
        }
    }
}

// ---------------------------------------------------------------------------
// Launch
// ---------------------------------------------------------------------------
extern "C" void kernel_launch(void* const* d_in, const int* in_sizes, int n_in,
                              void* d_out, int out_size) {
    const float* x      = (const float*)d_in[0];
    const float* h0     = (const float*)d_in[1];
    const float* c0     = (const float*)d_in[2];
    const float* w_ih_f = (const float*)d_in[3];
    const float* w_hh_f = (const float*)d_in[4];
    const float* b_ih_f = (const float*)d_in[5];
    const float* b_hh_f = (const float*)d_in[6];
    const float* w_ih_r = (const float*)d_in[7];
    const float* w_hh_r = (const float*)d_in[8];
    const float* b_ih_r = (const float*)d_in[9];
    const float* b_hh_r = (const float*)d_in[10];
    float* out = (float*)d_out;

    cudaFuncSetAttribute(lstm_persistent_kernel,
                         cudaFuncAttributeMaxDynamicSharedMemorySize, SMEM_TOTAL);

    dim3 ggrid(G4 / BN, (SEQT * BATCH) / BM, 2);   // (32, 256, 2)
    gemm_ih_kernel<<<ggrid, 256>>>(x, h0, w_ih_f, w_ih_r,
                                   b_ih_f, b_hh_f, b_ih_r, b_hh_r);

    lstm_persistent_kernel<<<NBLK, 256, SMEM_TOTAL>>>(
        w_hh_f, w_hh_r, c0, out);
}